// round 7
// baseline (speedup 1.0000x reference)
#include <cuda_runtime.h>
#include <math.h>
#include <stdint.h>

#define BATCH  4
#define SEQ    2048
#define DMODEL 1024
#define NHEAD  16
#define DHEAD  64
#define MROWS  (BATCH*SEQ)   // 8192

// Scratch (tf32-bit-pattern floats). g_V stored TRANSPOSED: [b, h, dh, s].
__device__ float g_Q [BATCH*NHEAD*SEQ*DHEAD];
__device__ float g_K [BATCH*NHEAD*SEQ*DHEAD];
__device__ float g_V [BATCH*NHEAD*SEQ*DHEAD];
__device__ float g_AO[(size_t)MROWS*DMODEL];
__device__ float g_X [(size_t)MROWS*DMODEL];
__device__ float g_W4[4][(size_t)DMODEL*DMODEL];   // transposed tf32 weights

// ---------------------------------------------------------------------------
__device__ __forceinline__ uint32_t f2tf32(float f) {
    uint32_t u;
    asm("cvt.rna.tf32.f32 %0, %1;" : "=r"(u) : "f"(f));
    return u;
}
__device__ __forceinline__ float ex2f(float x) {
    float r;
    asm("ex2.approx.ftz.f32 %0, %1;" : "=f"(r) : "f"(x));
    return r;
}
__device__ __forceinline__ void mma_tf32(float* d, const uint32_t* a,
                                         uint32_t b0, uint32_t b1) {
    asm volatile(
        "mma.sync.aligned.m16n8k8.row.col.f32.tf32.tf32.f32 "
        "{%0,%1,%2,%3}, {%4,%5,%6,%7}, {%8,%9}, {%0,%1,%2,%3};"
        : "+f"(d[0]), "+f"(d[1]), "+f"(d[2]), "+f"(d[3])
        : "r"(a[0]), "r"(a[1]), "r"(a[2]), "r"(a[3]),
          "r"(b0), "r"(b1));
}
__device__ __forceinline__ void ldsm_x4(uint32_t* r, uint32_t addr) {
    asm volatile("ldmatrix.sync.aligned.m8n8.x4.shared.b16 {%0,%1,%2,%3}, [%4];"
        : "=r"(r[0]), "=r"(r[1]), "=r"(r[2]), "=r"(r[3]) : "r"(addr));
}
__device__ __forceinline__ uint32_t smem_u32(const void* p) {
    uint32_t a;
    asm("{ .reg .u64 t; cvta.to.shared.u64 t, %1; cvt.u32.u64 %0, t; }" : "=r"(a) : "l"(p));
    return a;
}
__device__ __forceinline__ void cp_async16(uint32_t dst, const void* src) {
    asm volatile("cp.async.ca.shared.global [%0], [%1], 16;" :: "r"(dst), "l"(src));
}
__device__ __forceinline__ void cp_commit() {
    asm volatile("cp.async.commit_group;" ::: "memory");
}
template<int N>
__device__ __forceinline__ void cp_wait() {
    asm volatile("cp.async.wait_group %0;" :: "n"(N) : "memory");
}

// ---------------------------------------------------------------------------
__global__ void cvt_tf32_pass(const float* __restrict__ in,
                              float* __restrict__ outp, int n4) {
    const int i = blockIdx.x * blockDim.x + threadIdx.x;
    if (i < n4) {
        float4 v = *reinterpret_cast<const float4*>(in + (size_t)i * 4);
        uint4 u = { f2tf32(v.x), f2tf32(v.y), f2tf32(v.z), f2tf32(v.w) };
        *reinterpret_cast<uint4*>(outp + (size_t)i * 4) = u;
    }
}

// WT[n][k] = tf32(W[k][n])
__global__ void transpose_cvt(const float* __restrict__ W, float* __restrict__ WT) {
    __shared__ float tbuf[32][33];
    const int bx = blockIdx.x * 32, by = blockIdx.y * 32;
#pragma unroll
    for (int i = 0; i < 32; i += 8)
        tbuf[threadIdx.y + i][threadIdx.x] =
            W[(size_t)(by + threadIdx.y + i) * DMODEL + bx + threadIdx.x];
    __syncthreads();
#pragma unroll
    for (int i = 0; i < 32; i += 8)
        WT[(size_t)(bx + threadIdx.y + i) * DMODEL + by + threadIdx.x] =
            __uint_as_float(f2tf32(tbuf[threadIdx.x][threadIdx.y + i]));
}

// ---------------------------------------------------------------------------
// tf32 GEMM: C = A @ WT^T + bias. A[M][K] row-major, WT[N][K] row-major,
// both tf32-rounded. 3-stage cp.async; ALL fragments via ldmatrix.
// REMAP: 0 = plain [M][N], 1 = [b,h,s,dh], 2 = V-transposed [b,h,dh,s].
// ---------------------------------------------------------------------------
#define TPITCH 20
#define GSTAGES 3
#define T_ST (128*TPITCH)   // 2560 words per tile
#define GEMM_SMEM_BYTES (GSTAGES*2*T_ST*4)   // 61440

template<int REMAP, int CVTOUT>
__global__ __launch_bounds__(256) void gemm_mma(
    const float* __restrict__ A, const float* __restrict__ WT,
    const float* __restrict__ bias, float* __restrict__ C)
{
    extern __shared__ uint32_t su[];
    const uint32_t sbase = smem_u32(su);

    const int tid  = threadIdx.x;
    const int wid  = tid >> 5, lane = tid & 31;
    const int g    = lane >> 2, t = lane & 3;
    const int m0   = blockIdx.y * 128, n0 = blockIdx.x * 128;
    const int wm0  = (wid >> 2) * 64, wn0 = (wid & 3) * 32;

    // ldmatrix lane-source offsets
    const int arow_l = (lane & 7) + ((lane >> 3) & 1) * 8;   // A-frag
    const int acol_l = (lane >> 4) * 4;
    const int brow_l = (lane >> 4) * 8 + (lane & 7);          // B-frag
    const int bcol_l = ((lane >> 3) & 1) * 4;
    uint32_t aoff[4], boff[2];
#pragma unroll
    for (int mt = 0; mt < 4; mt++)
        aoff[mt] = (uint32_t)(((wm0 + mt * 16 + arow_l) * TPITCH + acol_l) * 4);
#pragma unroll
    for (int ntp = 0; ntp < 2; ntp++)
        boff[ntp] = (uint32_t)(((wn0 + ntp * 16 + brow_l) * TPITCH + bcol_l) * 4);

    // loaders: 512 chunks per tile / 256 threads = 2 each (A and B symmetric)
    const int lr[2] = { tid >> 2, (tid + 256) >> 2 };
    const int lc[2] = { (tid & 3) << 2, ((tid + 256) & 3) << 2 };

    auto issue = [&](int kt, int s) {
        const uint32_t abase = sbase + (uint32_t)(s * 2 * T_ST) * 4;
        const uint32_t bbase = abase + (uint32_t)T_ST * 4;
#pragma unroll
        for (int i = 0; i < 2; i++) {
            cp_async16(abase + (uint32_t)(lr[i] * TPITCH + lc[i]) * 4,
                       A + (size_t)(m0 + lr[i]) * DMODEL + kt * 16 + lc[i]);
            cp_async16(bbase + (uint32_t)(lr[i] * TPITCH + lc[i]) * 4,
                       WT + (size_t)(n0 + lr[i]) * DMODEL + kt * 16 + lc[i]);
        }
        cp_commit();
    };

    float acc[4][4][4];
#pragma unroll
    for (int mt = 0; mt < 4; mt++)
#pragma unroll
        for (int nt = 0; nt < 4; nt++)
#pragma unroll
            for (int r = 0; r < 4; r++) acc[mt][nt][r] = 0.f;

    issue(0, 0);
    issue(1, 1);

    const int NKT = DMODEL / 16;   // 64
    for (int kt = 0; kt < NKT; kt++) {
        const int s = kt % GSTAGES;
        if (kt + 1 < NKT) cp_wait<1>(); else cp_wait<0>();
        __syncthreads();
        if (kt + 2 < NKT) issue(kt + 2, (kt + 2) % GSTAGES);

        const uint32_t abase = sbase + (uint32_t)(s * 2 * T_ST) * 4;
        const uint32_t bbase = abase + (uint32_t)T_ST * 4;
#pragma unroll
        for (int ks = 0; ks < 2; ks++) {
            const uint32_t kb = (uint32_t)(ks * 8 * 4);
            uint32_t af[4][4], bf[2][4];
#pragma unroll
            for (int mt = 0; mt < 4; mt++)
                ldsm_x4(af[mt], abase + aoff[mt] + kb);
#pragma unroll
            for (int ntp = 0; ntp < 2; ntp++)
                ldsm_x4(bf[ntp], bbase + boff[ntp] + kb);
#pragma unroll
            for (int mt = 0; mt < 4; mt++)
#pragma unroll
                for (int ntp = 0; ntp < 2; ntp++) {
                    mma_tf32(acc[mt][2*ntp],   af[mt], bf[ntp][0], bf[ntp][1]);
                    mma_tf32(acc[mt][2*ntp+1], af[mt], bf[ntp][2], bf[ntp][3]);
                }
        }
    }

#pragma unroll
    for (int mt = 0; mt < 4; mt++) {
#pragma unroll
        for (int nt = 0; nt < 4; nt++) {
            const int row = m0 + wm0 + mt * 16 + g;
            const int col = n0 + wn0 + nt * 8 + t * 2;
            const float b0 = bias[col], b1 = bias[col + 1];
#pragma unroll
            for (int half = 0; half < 2; half++) {
                const int m = row + half * 8;
                float v0 = acc[mt][nt][half*2]   + b0;
                float v1 = acc[mt][nt][half*2+1] + b1;
                if (CVTOUT) {
                    v0 = __uint_as_float(f2tf32(v0));
                    v1 = __uint_as_float(f2tf32(v1));
                }
                if (REMAP == 2) {
                    // V transposed: [b, h, dh, s]
                    const int bb = m >> 11, ss = m & 2047;
                    const int hh = col >> 6, dd = col & 63;
                    float* vt = C + (((size_t)(bb * NHEAD + hh) * DHEAD + dd) * SEQ + ss);
                    vt[0]   = v0;
                    vt[SEQ] = v1;
                } else if (REMAP == 1) {
                    const int bb = m >> 11, ss = m & 2047;
                    const int hh = col >> 6, dd = col & 63;
                    float* outp = C + (((size_t)(bb * NHEAD + hh) * SEQ + ss) * DHEAD + dd);
                    *reinterpret_cast<float2*>(outp) = make_float2(v0, v1);
                } else {
                    float* outp = C + (size_t)m * DMODEL + col;
                    *reinterpret_cast<float2*>(outp) = make_float2(v0, v1);
                }
            }
        }
    }
}

// ---------------------------------------------------------------------------
// Flash attention, tf32 mma.sync, ALL fragments via ldmatrix.
// V is stored transposed [b,h,dh,s]; V tile in smem is [dh=64][kv=64].
// log2-domain softmax (ex2.approx).
// ---------------------------------------------------------------------------
#define QP 68
#define FQ_OFF 0
#define FK_OFF 4352
#define FK_ST  4352
#define FV_OFF 13056
#define FV_ST  4352
#define FP_OFF 21760
#define FA_SMEM_BYTES ((FP_OFF + 4352) * 4)   // 104448

#define SSCALE 0.18033688011112042f   // 0.125 * log2(e)

__global__ __launch_bounds__(128) void flash_attn_mma(
    const float* __restrict__ Q, const float* __restrict__ K,
    const float* __restrict__ V, float* __restrict__ AO,
    const int* __restrict__ maskp)
{
    extern __shared__ uint32_t su[];
    const uint32_t sbase = smem_u32(su);
    uint32_t* Ps = su + FP_OFF;

    const int tid = threadIdx.x;
    const int wid = tid >> 5, lane = tid & 31;
    const int g = lane >> 2, t = lane & 3;
    const int qt = blockIdx.x, hh = blockIdx.y, bb = blockIdx.z;
    const int q0 = qt * 64;
    const int wr0 = wid * 16;
    const size_t bh = ((size_t)bb*NHEAD + hh) * SEQ * DHEAD;
    const int causal = (maskp[0] != 0);
    const int ktmax = causal ? qt : (SEQ/64 - 1);

    const int arow_l = (lane & 7) + ((lane >> 3) & 1) * 8;
    const int acol_l = (lane >> 4) * 4;
    const int brow_l = (lane >> 4) * 8 + (lane & 7);
    const int bcol_l = ((lane >> 3) & 1) * 4;
    const uint32_t qoff = (uint32_t)(((wr0 + arow_l) * QP + acol_l) * 4);
    const uint32_t koff = (uint32_t)((brow_l * QP + bcol_l) * 4);

    auto issue_kv = [&](int kt, int s) {
        const float* Kg = K + bh + (size_t)kt*64*DHEAD;
        const float* Vg = V + bh;   // transposed: [dh][s]
        const uint32_t kb = sbase + (uint32_t)(FK_OFF + s*FK_ST) * 4;
        const uint32_t vb = sbase + (uint32_t)(FV_OFF + s*FV_ST) * 4;
#pragma unroll
        for (int i = 0; i < 8; i++) {
            const int c = tid + i * 128;
            const int r = c >> 4, col = (c & 15) * 4;
            cp_async16(kb + (uint32_t)(r*QP + col) * 4, Kg + r*DHEAD + col);
            cp_async16(vb + (uint32_t)(r*QP + col) * 4,
                       Vg + (size_t)r*SEQ + kt*64 + col);
        }
        cp_commit();
    };

    {   // Q tile + KV stage 0 as group 0
        const float* Qg = Q + bh + (size_t)q0 * DHEAD;
#pragma unroll
        for (int i = 0; i < 8; i++) {
            const int c = tid + i * 128;
            const int r = c >> 4, col = (c & 15) * 4;
            cp_async16(sbase + (uint32_t)(r*QP + col) * 4, Qg + r*DHEAD + col);
        }
        const float* Kg = K + bh;
        const float* Vg = V + bh;
        const uint32_t kb = sbase + (uint32_t)FK_OFF * 4;
        const uint32_t vb = sbase + (uint32_t)FV_OFF * 4;
#pragma unroll
        for (int i = 0; i < 8; i++) {
            const int c = tid + i * 128;
            const int r = c >> 4, col = (c & 15) * 4;
            cp_async16(kb + (uint32_t)(r*QP + col) * 4, Kg + r*DHEAD + col);
            cp_async16(vb + (uint32_t)(r*QP + col) * 4, Vg + (size_t)r*SEQ + col);
        }
        cp_commit();
    }
    if (ktmax >= 1) issue_kv(1, 1);

    float m_i[2] = { -INFINITY, -INFINITY };
    float l_i[2] = { 0.f, 0.f };
    float accO[8][4];
#pragma unroll
    for (int nt = 0; nt < 8; nt++)
#pragma unroll
        for (int c = 0; c < 4; c++) accO[nt][c] = 0.f;

    for (int kt = 0; kt <= ktmax; kt++) {
        const int s = kt & 1;
        if (kt < ktmax) cp_wait<1>(); else cp_wait<0>();
        __syncthreads();

        const uint32_t kbase = sbase + (uint32_t)(FK_OFF + s*FK_ST) * 4;
        const uint32_t vbase = sbase + (uint32_t)(FV_OFF + s*FV_ST) * 4;

        // S = Q @ K^T (warp: 16x64), scores in log2 units
        float accS[8][4];
#pragma unroll
        for (int nt = 0; nt < 8; nt++)
#pragma unroll
            for (int c = 0; c < 4; c++) accS[nt][c] = 0.f;
#pragma unroll
        for (int kc = 0; kc < 8; kc++) {
            uint32_t af[4];
            ldsm_x4(af, sbase + qoff + (uint32_t)(kc * 32));
#pragma unroll
            for (int ntp = 0; ntp < 4; ntp++) {
                uint32_t kr[4];
                ldsm_x4(kr, kbase + (uint32_t)(ntp * 16 * QP * 4) + koff
                            + (uint32_t)(kc * 32));
                mma_tf32(accS[2*ntp],   af, kr[0], kr[1]);
                mma_tf32(accS[2*ntp+1], af, kr[2], kr[3]);
            }
        }

        const bool diag = causal && (kt == qt);
#pragma unroll
        for (int nt = 0; nt < 8; nt++)
#pragma unroll
            for (int c = 0; c < 4; c++) {
                float sv = accS[nt][c] * SSCALE;
                if (diag) {
                    const int grow = q0 + wr0 + g + ((c & 2) ? 8 : 0);
                    const int gcol = kt*64 + nt*8 + 2*t + (c & 1);
                    if (gcol > grow) sv = -INFINITY;
                }
                accS[nt][c] = sv;
            }

#pragma unroll
        for (int r = 0; r < 2; r++) {
            float rmax = -INFINITY;
#pragma unroll
            for (int nt = 0; nt < 8; nt++)
                rmax = fmaxf(rmax, fmaxf(accS[nt][2*r], accS[nt][2*r+1]));
            rmax = fmaxf(rmax, __shfl_xor_sync(0xffffffffu, rmax, 1));
            rmax = fmaxf(rmax, __shfl_xor_sync(0xffffffffu, rmax, 2));
            const float mnew = fmaxf(m_i[r], rmax);
            const float corr = ex2f(m_i[r] - mnew);
            m_i[r] = mnew;
            float rsum = 0.f;
#pragma unroll
            for (int nt = 0; nt < 8; nt++) {
                const float p0 = ex2f(accS[nt][2*r]   - mnew);
                const float p1 = ex2f(accS[nt][2*r+1] - mnew);
                accS[nt][2*r] = p0; accS[nt][2*r+1] = p1;
                rsum += p0 + p1;
            }
            rsum += __shfl_xor_sync(0xffffffffu, rsum, 1);
            rsum += __shfl_xor_sync(0xffffffffu, rsum, 2);
            l_i[r] = l_i[r] * corr + rsum;
#pragma unroll
            for (int nt = 0; nt < 8; nt++) {
                accO[nt][2*r]   *= corr;
                accO[nt][2*r+1] *= corr;
            }
        }

        // stage P (tf32) into warp-private SMEM rows
#pragma unroll
        for (int nt = 0; nt < 8; nt++) {
            uint32_t* pr0 = Ps + (wr0 + g)*QP     + nt*8 + 2*t;
            uint32_t* pr1 = Ps + (wr0 + g + 8)*QP + nt*8 + 2*t;
            pr0[0] = f2tf32(accS[nt][0]); pr0[1] = f2tf32(accS[nt][1]);
            pr1[0] = f2tf32(accS[nt][2]); pr1[1] = f2tf32(accS[nt][3]);
        }
        __syncwarp();

        // O += P @ V  (V tile is [dh][kv], B-frags via ldmatrix)
        const uint32_t pbase = sbase + (uint32_t)FP_OFF * 4;
#pragma unroll
        for (int kc = 0; kc < 8; kc++) {
            uint32_t af[4];
            ldsm_x4(af, pbase + qoff + (uint32_t)(kc * 32));
#pragma unroll
            for (int ntp = 0; ntp < 4; ntp++) {
                uint32_t vr[4];
                ldsm_x4(vr, vbase + (uint32_t)(ntp * 16 * QP * 4) + koff
                            + (uint32_t)(kc * 32));
                mma_tf32(accO[2*ntp],   af, vr[0], vr[1]);
                mma_tf32(accO[2*ntp+1], af, vr[2], vr[3]);
            }
        }

        __syncthreads();
        if (kt + 2 <= ktmax) issue_kv(kt + 2, s);
    }

    const float inv0 = 1.f / l_i[0];
    const float inv1 = 1.f / l_i[1];
    const int row0 = q0 + wr0 + g;
    float* outb = AO + ((size_t)bb*SEQ + row0)*DMODEL + hh*DHEAD;
#pragma unroll
    for (int nt = 0; nt < 8; nt++) {
        const int col = nt*8 + 2*t;
        float2 o0 = make_float2(__uint_as_float(f2tf32(accO[nt][0]*inv0)),
                                __uint_as_float(f2tf32(accO[nt][1]*inv0)));
        float2 o1 = make_float2(__uint_as_float(f2tf32(accO[nt][2]*inv1)),
                                __uint_as_float(f2tf32(accO[nt][3]*inv1)));
        *reinterpret_cast<float2*>(outb + col) = o0;
        *reinterpret_cast<float2*>(outb + 8*DMODEL + col) = o1;
    }
}

// ---------------------------------------------------------------------------
extern "C" void kernel_launch(void* const* d_in, const int* in_sizes, int n_in,
                              void* d_out, int out_size)
{
    const float* x    = (const float*)d_in[0];
    const float* Wq   = (const float*)d_in[1];
    const float* bq   = (const float*)d_in[2];
    const float* Wk   = (const float*)d_in[3];
    const float* bk   = (const float*)d_in[4];
    const float* Wv   = (const float*)d_in[5];
    const float* bv   = (const float*)d_in[6];
    const float* Wo   = (const float*)d_in[7];
    const float* bo   = (const float*)d_in[8];
    const int*   mask = (const int*)  d_in[9];
    float* out = (float*)d_out;

    float *Qp, *Kp, *Vp, *AOp, *Xp, *Wp;
    cudaGetSymbolAddress((void**)&Qp,  g_Q);
    cudaGetSymbolAddress((void**)&Kp,  g_K);
    cudaGetSymbolAddress((void**)&Vp,  g_V);
    cudaGetSymbolAddress((void**)&AOp, g_AO);
    cudaGetSymbolAddress((void**)&Xp,  g_X);
    cudaGetSymbolAddress((void**)&Wp,  g_W4);
    float* WqT = Wp + 0 * (size_t)DMODEL*DMODEL;
    float* WkT = Wp + 1 * (size_t)DMODEL*DMODEL;
    float* WvT = Wp + 2 * (size_t)DMODEL*DMODEL;
    float* WoT = Wp + 3 * (size_t)DMODEL*DMODEL;

    cudaFuncSetAttribute(gemm_mma<1,1>, cudaFuncAttributeMaxDynamicSharedMemorySize, GEMM_SMEM_BYTES);
    cudaFuncSetAttribute(gemm_mma<2,1>, cudaFuncAttributeMaxDynamicSharedMemorySize, GEMM_SMEM_BYTES);
    cudaFuncSetAttribute(gemm_mma<0,0>, cudaFuncAttributeMaxDynamicSharedMemorySize, GEMM_SMEM_BYTES);
    cudaFuncSetAttribute(flash_attn_mma, cudaFuncAttributeMaxDynamicSharedMemorySize, FA_SMEM_BYTES);

    const int nx4 = MROWS * DMODEL / 4;
    cvt_tf32_pass<<<(nx4 + 255)/256, 256>>>(x, Xp, nx4);
    dim3 tb(32, 8), tg(32, 32);
    transpose_cvt<<<tg, tb>>>(Wq, WqT);
    transpose_cvt<<<tg, tb>>>(Wk, WkT);
    transpose_cvt<<<tg, tb>>>(Wv, WvT);
    transpose_cvt<<<tg, tb>>>(Wo, WoT);

    dim3 gg(DMODEL/128, MROWS/128);   // (8, 64)
    gemm_mma<1,1><<<gg, 256, GEMM_SMEM_BYTES>>>(Xp, WqT, bq, Qp);
    gemm_mma<1,1><<<gg, 256, GEMM_SMEM_BYTES>>>(Xp, WkT, bk, Kp);
    gemm_mma<2,1><<<gg, 256, GEMM_SMEM_BYTES>>>(Xp, WvT, bv, Vp);   // V transposed

    dim3 gattn(SEQ/64, NHEAD, BATCH);  // (32, 16, 4)
    flash_attn_mma<<<gattn, 128, FA_SMEM_BYTES>>>(Qp, Kp, Vp, AOp, mask);

    gemm_mma<0,0><<<gg, 256, GEMM_SMEM_BYTES>>>(AOp, WoT, bo, out);
}

// round 8
// speedup vs baseline: 1.1411x; 1.1411x over previous
#include <cuda_runtime.h>
#include <math.h>
#include <stdint.h>

#define BATCH  4
#define SEQ    2048
#define DMODEL 1024
#define NHEAD  16
#define DHEAD  64
#define MROWS  (BATCH*SEQ)   // 8192

// Scratch (tf32-bit-pattern floats). g_V stored TRANSPOSED: [b, h, dh, s].
// g_Q additionally pre-scaled by 0.125*log2(e).
__device__ float g_Q [BATCH*NHEAD*SEQ*DHEAD];
__device__ float g_K [BATCH*NHEAD*SEQ*DHEAD];
__device__ float g_V [BATCH*NHEAD*SEQ*DHEAD];
__device__ float g_AO[(size_t)MROWS*DMODEL];
__device__ float g_X [(size_t)MROWS*DMODEL];
__device__ float g_W4[4][(size_t)DMODEL*DMODEL];

#define SSCALE 0.18033688011112042f   // 0.125 * log2(e)

// ---------------------------------------------------------------------------
__device__ __forceinline__ uint32_t f2tf32(float f) {
    uint32_t u;
    asm("cvt.rna.tf32.f32 %0, %1;" : "=r"(u) : "f"(f));
    return u;
}
__device__ __forceinline__ float ex2f(float x) {
    float r;
    asm("ex2.approx.ftz.f32 %0, %1;" : "=f"(r) : "f"(x));
    return r;
}
__device__ __forceinline__ void mma_tf32(float* d, const uint32_t* a,
                                         uint32_t b0, uint32_t b1) {
    asm volatile(
        "mma.sync.aligned.m16n8k8.row.col.f32.tf32.tf32.f32 "
        "{%0,%1,%2,%3}, {%4,%5,%6,%7}, {%8,%9}, {%0,%1,%2,%3};"
        : "+f"(d[0]), "+f"(d[1]), "+f"(d[2]), "+f"(d[3])
        : "r"(a[0]), "r"(a[1]), "r"(a[2]), "r"(a[3]),
          "r"(b0), "r"(b1));
}
__device__ __forceinline__ void ldsm_x4(uint32_t* r, uint32_t addr) {
    asm volatile("ldmatrix.sync.aligned.m8n8.x4.shared.b16 {%0,%1,%2,%3}, [%4];"
        : "=r"(r[0]), "=r"(r[1]), "=r"(r[2]), "=r"(r[3]) : "r"(addr));
}
__device__ __forceinline__ uint32_t smem_u32(const void* p) {
    uint32_t a;
    asm("{ .reg .u64 t; cvta.to.shared.u64 t, %1; cvt.u32.u64 %0, t; }" : "=r"(a) : "l"(p));
    return a;
}
__device__ __forceinline__ void cp_async16(uint32_t dst, const void* src) {
    asm volatile("cp.async.ca.shared.global [%0], [%1], 16;" :: "r"(dst), "l"(src));
}
__device__ __forceinline__ void cp_commit() {
    asm volatile("cp.async.commit_group;" ::: "memory");
}
template<int N>
__device__ __forceinline__ void cp_wait() {
    asm volatile("cp.async.wait_group %0;" :: "n"(N) : "memory");
}

// ---------------------------------------------------------------------------
__global__ void cvt_tf32_pass(const float* __restrict__ in,
                              float* __restrict__ outp, int n4) {
    const int i = blockIdx.x * blockDim.x + threadIdx.x;
    if (i < n4) {
        float4 v = *reinterpret_cast<const float4*>(in + (size_t)i * 4);
        uint4 u = { f2tf32(v.x), f2tf32(v.y), f2tf32(v.z), f2tf32(v.w) };
        *reinterpret_cast<uint4*>(outp + (size_t)i * 4) = u;
    }
}

// WT[n][k] = tf32(W[k][n]) for 4 weight matrices (z = which)
__global__ void transpose_cvt4(const float* __restrict__ W0,
                               const float* __restrict__ W1,
                               const float* __restrict__ W2,
                               const float* __restrict__ W3,
                               float* __restrict__ WT) {
    __shared__ float tbuf[32][33];
    const float* W = (blockIdx.z == 0) ? W0 : (blockIdx.z == 1) ? W1
                   : (blockIdx.z == 2) ? W2 : W3;
    float* T = WT + (size_t)blockIdx.z * DMODEL * DMODEL;
    const int bx = blockIdx.x * 32, by = blockIdx.y * 32;
#pragma unroll
    for (int i = 0; i < 32; i += 8)
        tbuf[threadIdx.y + i][threadIdx.x] =
            W[(size_t)(by + threadIdx.y + i) * DMODEL + bx + threadIdx.x];
    __syncthreads();
#pragma unroll
    for (int i = 0; i < 32; i += 8)
        T[(size_t)(bx + threadIdx.y + i) * DMODEL + by + threadIdx.x] =
            __uint_as_float(f2tf32(tbuf[threadIdx.x][threadIdx.y + i]));
}

// ---------------------------------------------------------------------------
// tf32 GEMM: C = (A @ WT^T + bias) * oscale. BK=32, 2-stage cp.async.
// REMAP: 0 = plain [M][N], 1 = [b,h,s,dh], 2 = V-transposed [b,h,dh,s].
// ---------------------------------------------------------------------------
#define TPITCH 36
#define T_ST (128*TPITCH)    // 4608 words per tile
#define GEMM_SMEM_BYTES (2*2*T_ST*4)   // 73728

template<int REMAP, int CVTOUT>
__global__ __launch_bounds__(256) void gemm_mma(
    const float* __restrict__ A, const float* __restrict__ WT,
    const float* __restrict__ bias, float* __restrict__ C, float oscale)
{
    extern __shared__ uint32_t su[];
    const uint32_t sbase = smem_u32(su);

    const int tid  = threadIdx.x;
    const int wid  = tid >> 5, lane = tid & 31;
    const int g    = lane >> 2, t = lane & 3;
    const int m0   = blockIdx.y * 128, n0 = blockIdx.x * 128;
    const int wm0  = (wid >> 2) * 64, wn0 = (wid & 3) * 32;

    const int arow_l = (lane & 7) + ((lane >> 3) & 1) * 8;
    const int acol_l = (lane >> 4) * 4;
    const int brow_l = (lane >> 4) * 8 + (lane & 7);
    const int bcol_l = ((lane >> 3) & 1) * 4;
    uint32_t aoff[4], boff[2];
#pragma unroll
    for (int mt = 0; mt < 4; mt++)
        aoff[mt] = (uint32_t)(((wm0 + mt * 16 + arow_l) * TPITCH + acol_l) * 4);
#pragma unroll
    for (int ntp = 0; ntp < 2; ntp++)
        boff[ntp] = (uint32_t)(((wn0 + ntp * 16 + brow_l) * TPITCH + bcol_l) * 4);

    // loaders: 1024 float4 chunks per tile, 4 per thread
    int lr[4], lc[4];
#pragma unroll
    for (int i = 0; i < 4; i++) {
        const int c = tid + i * 256;
        lr[i] = c >> 3;
        lc[i] = (c & 7) * 4;
    }

    auto issue = [&](int kt, int s) {
        const uint32_t abase = sbase + (uint32_t)(s * 2 * T_ST) * 4;
        const uint32_t bbase = abase + (uint32_t)T_ST * 4;
#pragma unroll
        for (int i = 0; i < 4; i++) {
            cp_async16(abase + (uint32_t)(lr[i] * TPITCH + lc[i]) * 4,
                       A + (size_t)(m0 + lr[i]) * DMODEL + kt * 32 + lc[i]);
            cp_async16(bbase + (uint32_t)(lr[i] * TPITCH + lc[i]) * 4,
                       WT + (size_t)(n0 + lr[i]) * DMODEL + kt * 32 + lc[i]);
        }
        cp_commit();
    };

    float acc[4][4][4];
#pragma unroll
    for (int mt = 0; mt < 4; mt++)
#pragma unroll
        for (int nt = 0; nt < 4; nt++)
#pragma unroll
            for (int r = 0; r < 4; r++) acc[mt][nt][r] = 0.f;

    issue(0, 0);

    const int NKT = DMODEL / 32;   // 32
    for (int kt = 0; kt < NKT; kt++) {
        const int s = kt & 1;
        cp_wait<0>();
        __syncthreads();
        if (kt + 1 < NKT) issue(kt + 1, s ^ 1);

        const uint32_t abase = sbase + (uint32_t)(s * 2 * T_ST) * 4;
        const uint32_t bbase = abase + (uint32_t)T_ST * 4;
#pragma unroll
        for (int ks = 0; ks < 4; ks++) {
            const uint32_t kb = (uint32_t)(ks * 32);
            uint32_t af[4][4], bf[2][4];
#pragma unroll
            for (int mt = 0; mt < 4; mt++)
                ldsm_x4(af[mt], abase + aoff[mt] + kb);
#pragma unroll
            for (int ntp = 0; ntp < 2; ntp++)
                ldsm_x4(bf[ntp], bbase + boff[ntp] + kb);
#pragma unroll
            for (int mt = 0; mt < 4; mt++)
#pragma unroll
                for (int ntp = 0; ntp < 2; ntp++) {
                    mma_tf32(acc[mt][2*ntp],   af[mt], bf[ntp][0], bf[ntp][1]);
                    mma_tf32(acc[mt][2*ntp+1], af[mt], bf[ntp][2], bf[ntp][3]);
                }
        }
    }

#pragma unroll
    for (int mt = 0; mt < 4; mt++) {
#pragma unroll
        for (int nt = 0; nt < 4; nt++) {
            const int row = m0 + wm0 + mt * 16 + g;
            const int col = n0 + wn0 + nt * 8 + t * 2;
            const float b0 = bias[col], b1 = bias[col + 1];
#pragma unroll
            for (int half = 0; half < 2; half++) {
                const int m = row + half * 8;
                float v0 = (acc[mt][nt][half*2]   + b0) * oscale;
                float v1 = (acc[mt][nt][half*2+1] + b1) * oscale;
                if (CVTOUT) {
                    v0 = __uint_as_float(f2tf32(v0));
                    v1 = __uint_as_float(f2tf32(v1));
                }
                if (REMAP == 2) {
                    const int bb = m >> 11, ss = m & 2047;
                    const int hh = col >> 6, dd = col & 63;
                    float* vt = C + (((size_t)(bb * NHEAD + hh) * DHEAD + dd) * SEQ + ss);
                    vt[0]   = v0;
                    vt[SEQ] = v1;
                } else if (REMAP == 1) {
                    const int bb = m >> 11, ss = m & 2047;
                    const int hh = col >> 6, dd = col & 63;
                    float* outp = C + (((size_t)(bb * NHEAD + hh) * SEQ + ss) * DHEAD + dd);
                    *reinterpret_cast<float2*>(outp) = make_float2(v0, v1);
                } else {
                    float* outp = C + (size_t)m * DMODEL + col;
                    *reinterpret_cast<float2*>(outp) = make_float2(v0, v1);
                }
            }
        }
    }
}

// ---------------------------------------------------------------------------
// Flash attention: single-buffered K and V with split overlap windows.
// smem 69632 B -> 3 CTAs/SM. Q pre-scaled; scores already in log2 units.
// ---------------------------------------------------------------------------
#define QP 68
#define FQ_OFF 0
#define FK_OFF 4352
#define FV_OFF 8704
#define FP_OFF 13056
#define FA_SMEM_BYTES ((FP_OFF + 4352) * 4)   // 69632

__global__ __launch_bounds__(128) void flash_attn_mma(
    const float* __restrict__ Q, const float* __restrict__ K,
    const float* __restrict__ V, float* __restrict__ AO,
    const int* __restrict__ maskp)
{
    extern __shared__ uint32_t su[];
    const uint32_t sbase = smem_u32(su);
    uint32_t* Ps = su + FP_OFF;

    const int tid = threadIdx.x;
    const int wid = tid >> 5, lane = tid & 31;
    const int g = lane >> 2, t = lane & 3;
    const int qt = blockIdx.x, hh = blockIdx.y, bb = blockIdx.z;
    const int q0 = qt * 64;
    const int wr0 = wid * 16;
    const size_t bh = ((size_t)bb*NHEAD + hh) * SEQ * DHEAD;
    const int causal = (maskp[0] != 0);
    const int ktmax = causal ? qt : (SEQ/64 - 1);

    const int arow_l = (lane & 7) + ((lane >> 3) & 1) * 8;
    const int acol_l = (lane >> 4) * 4;
    const int brow_l = (lane >> 4) * 8 + (lane & 7);
    const int bcol_l = ((lane >> 3) & 1) * 4;
    const uint32_t qoff = (uint32_t)(((wr0 + arow_l) * QP + acol_l) * 4);
    const uint32_t koff = (uint32_t)((brow_l * QP + bcol_l) * 4);

    const uint32_t kbase = sbase + (uint32_t)FK_OFF * 4;
    const uint32_t vbase = sbase + (uint32_t)FV_OFF * 4;

    auto issue_k = [&](int kt) {
        const float* Kg = K + bh + (size_t)kt*64*DHEAD;
#pragma unroll
        for (int i = 0; i < 8; i++) {
            const int c = tid + i * 128;
            const int r = c >> 4, col = (c & 15) * 4;
            cp_async16(kbase + (uint32_t)(r*QP + col) * 4, Kg + r*DHEAD + col);
        }
        cp_commit();
    };
    auto issue_v = [&](int kt) {
        const float* Vg = V + bh;   // transposed [dh][s]
#pragma unroll
        for (int i = 0; i < 8; i++) {
            const int c = tid + i * 128;
            const int r = c >> 4, col = (c & 15) * 4;
            cp_async16(vbase + (uint32_t)(r*QP + col) * 4,
                       Vg + (size_t)r*SEQ + kt*64 + col);
        }
        cp_commit();
    };

    {   // prologue: group0 = Q + K0, group1 = V0
        const float* Qg = Q + bh + (size_t)q0 * DHEAD;
#pragma unroll
        for (int i = 0; i < 8; i++) {
            const int c = tid + i * 128;
            const int r = c >> 4, col = (c & 15) * 4;
            cp_async16(sbase + (uint32_t)(r*QP + col) * 4, Qg + r*DHEAD + col);
        }
        issue_k(0);   // commits Q+K0 together
        issue_v(0);
    }

    float m_i[2] = { -INFINITY, -INFINITY };
    float l_i[2] = { 0.f, 0.f };
    float accO[8][4];
#pragma unroll
    for (int nt = 0; nt < 8; nt++)
#pragma unroll
        for (int c = 0; c < 4; c++) accO[nt][c] = 0.f;

    for (int kt = 0; kt <= ktmax; kt++) {
        // K_kt (and Q) ready; V_kt may still be in flight
        cp_wait<1>();
        __syncthreads();

        // S = Q @ K^T (warp: 16x64), log2-domain scores
        float accS[8][4];
#pragma unroll
        for (int nt = 0; nt < 8; nt++)
#pragma unroll
            for (int c = 0; c < 4; c++) accS[nt][c] = 0.f;
#pragma unroll
        for (int kc = 0; kc < 8; kc++) {
            uint32_t af[4];
            ldsm_x4(af, sbase + qoff + (uint32_t)(kc * 32));
#pragma unroll
            for (int ntp = 0; ntp < 4; ntp++) {
                uint32_t kr[4];
                ldsm_x4(kr, kbase + (uint32_t)(ntp * 16 * QP * 4) + koff
                            + (uint32_t)(kc * 32));
                mma_tf32(accS[2*ntp],   af, kr[0], kr[1]);
                mma_tf32(accS[2*ntp+1], af, kr[2], kr[3]);
            }
        }

        __syncthreads();                    // K buffer free
        if (kt + 1 <= ktmax) issue_k(kt + 1);

        const bool diag = causal && (kt == qt);
        if (diag) {
#pragma unroll
            for (int nt = 0; nt < 8; nt++)
#pragma unroll
                for (int c = 0; c < 4; c++) {
                    const int grow = q0 + wr0 + g + ((c & 2) ? 8 : 0);
                    const int gcol = kt*64 + nt*8 + 2*t + (c & 1);
                    if (gcol > grow) accS[nt][c] = -INFINITY;
                }
        }

#pragma unroll
        for (int r = 0; r < 2; r++) {
            float rmax = -INFINITY;
#pragma unroll
            for (int nt = 0; nt < 8; nt++)
                rmax = fmaxf(rmax, fmaxf(accS[nt][2*r], accS[nt][2*r+1]));
            rmax = fmaxf(rmax, __shfl_xor_sync(0xffffffffu, rmax, 1));
            rmax = fmaxf(rmax, __shfl_xor_sync(0xffffffffu, rmax, 2));
            const float mnew = fmaxf(m_i[r], rmax);
            const float corr = ex2f(m_i[r] - mnew);
            m_i[r] = mnew;
            float rsum = 0.f;
#pragma unroll
            for (int nt = 0; nt < 8; nt++) {
                const float p0 = ex2f(accS[nt][2*r]   - mnew);
                const float p1 = ex2f(accS[nt][2*r+1] - mnew);
                accS[nt][2*r] = p0; accS[nt][2*r+1] = p1;
                rsum += p0 + p1;
            }
            rsum += __shfl_xor_sync(0xffffffffu, rsum, 1);
            rsum += __shfl_xor_sync(0xffffffffu, rsum, 2);
            l_i[r] = l_i[r] * corr + rsum;
#pragma unroll
            for (int nt = 0; nt < 8; nt++) {
                accO[nt][2*r]   *= corr;
                accO[nt][2*r+1] *= corr;
            }
        }

        // stage P (tf32), warp-private rows
#pragma unroll
        for (int nt = 0; nt < 8; nt++) {
            uint32_t* pr0 = Ps + (wr0 + g)*QP     + nt*8 + 2*t;
            uint32_t* pr1 = Ps + (wr0 + g + 8)*QP + nt*8 + 2*t;
            pr0[0] = f2tf32(accS[nt][0]); pr0[1] = f2tf32(accS[nt][1]);
            pr1[0] = f2tf32(accS[nt][2]); pr1[1] = f2tf32(accS[nt][3]);
        }
        __syncwarp();

        // V_kt ready (pending: K_{kt+1} if issued)
        if (kt < ktmax) cp_wait<1>(); else cp_wait<0>();
        __syncthreads();

        // O += P @ V (V tile [dh][kv])
        const uint32_t pbase = sbase + (uint32_t)FP_OFF * 4;
#pragma unroll
        for (int kc = 0; kc < 8; kc++) {
            uint32_t af[4];
            ldsm_x4(af, pbase + qoff + (uint32_t)(kc * 32));
#pragma unroll
            for (int ntp = 0; ntp < 4; ntp++) {
                uint32_t vr[4];
                ldsm_x4(vr, vbase + (uint32_t)(ntp * 16 * QP * 4) + koff
                            + (uint32_t)(kc * 32));
                mma_tf32(accO[2*ntp],   af, vr[0], vr[1]);
                mma_tf32(accO[2*ntp+1], af, vr[2], vr[3]);
            }
        }

        __syncthreads();                    // V buffer free
        if (kt + 1 <= ktmax) issue_v(kt + 1);
    }

    const float inv0 = 1.f / l_i[0];
    const float inv1 = 1.f / l_i[1];
    const int row0 = q0 + wr0 + g;
    float* outb = AO + ((size_t)bb*SEQ + row0)*DMODEL + hh*DHEAD;
#pragma unroll
    for (int nt = 0; nt < 8; nt++) {
        const int col = nt*8 + 2*t;
        float2 o0 = make_float2(__uint_as_float(f2tf32(accO[nt][0]*inv0)),
                                __uint_as_float(f2tf32(accO[nt][1]*inv0)));
        float2 o1 = make_float2(__uint_as_float(f2tf32(accO[nt][2]*inv1)),
                                __uint_as_float(f2tf32(accO[nt][3]*inv1)));
        *reinterpret_cast<float2*>(outb + col) = o0;
        *reinterpret_cast<float2*>(outb + 8*DMODEL + col) = o1;
    }
}

// ---------------------------------------------------------------------------
extern "C" void kernel_launch(void* const* d_in, const int* in_sizes, int n_in,
                              void* d_out, int out_size)
{
    const float* x    = (const float*)d_in[0];
    const float* Wq   = (const float*)d_in[1];
    const float* bq   = (const float*)d_in[2];
    const float* Wk   = (const float*)d_in[3];
    const float* bk   = (const float*)d_in[4];
    const float* Wv   = (const float*)d_in[5];
    const float* bv   = (const float*)d_in[6];
    const float* Wo   = (const float*)d_in[7];
    const float* bo   = (const float*)d_in[8];
    const int*   mask = (const int*)  d_in[9];
    float* out = (float*)d_out;

    float *Qp, *Kp, *Vp, *AOp, *Xp, *Wp;
    cudaGetSymbolAddress((void**)&Qp,  g_Q);
    cudaGetSymbolAddress((void**)&Kp,  g_K);
    cudaGetSymbolAddress((void**)&Vp,  g_V);
    cudaGetSymbolAddress((void**)&AOp, g_AO);
    cudaGetSymbolAddress((void**)&Xp,  g_X);
    cudaGetSymbolAddress((void**)&Wp,  g_W4);
    float* WqT = Wp + 0 * (size_t)DMODEL*DMODEL;
    float* WkT = Wp + 1 * (size_t)DMODEL*DMODEL;
    float* WvT = Wp + 2 * (size_t)DMODEL*DMODEL;
    float* WoT = Wp + 3 * (size_t)DMODEL*DMODEL;

    cudaFuncSetAttribute(gemm_mma<1,1>, cudaFuncAttributeMaxDynamicSharedMemorySize, GEMM_SMEM_BYTES);
    cudaFuncSetAttribute(gemm_mma<2,1>, cudaFuncAttributeMaxDynamicSharedMemorySize, GEMM_SMEM_BYTES);
    cudaFuncSetAttribute(gemm_mma<0,0>, cudaFuncAttributeMaxDynamicSharedMemorySize, GEMM_SMEM_BYTES);
    cudaFuncSetAttribute(flash_attn_mma, cudaFuncAttributeMaxDynamicSharedMemorySize, FA_SMEM_BYTES);

    const int nx4 = MROWS * DMODEL / 4;
    cvt_tf32_pass<<<(nx4 + 255)/256, 256>>>(x, Xp, nx4);
    dim3 tb(32, 8), tg4(32, 32, 4);
    transpose_cvt4<<<tg4, tb>>>(Wq, Wk, Wv, Wo, Wp);

    dim3 gg(DMODEL/128, MROWS/128);   // (8, 64)
    gemm_mma<1,1><<<gg, 256, GEMM_SMEM_BYTES>>>(Xp, WqT, bq, Qp, SSCALE);
    gemm_mma<1,1><<<gg, 256, GEMM_SMEM_BYTES>>>(Xp, WkT, bk, Kp, 1.0f);
    gemm_mma<2,1><<<gg, 256, GEMM_SMEM_BYTES>>>(Xp, WvT, bv, Vp, 1.0f);

    dim3 gattn(SEQ/64, NHEAD, BATCH);  // (32, 16, 4)
    flash_attn_mma<<<gattn, 128, FA_SMEM_BYTES>>>(Qp, Kp, Vp, AOp, mask);

    gemm_mma<0,0><<<gg, 256, GEMM_SMEM_BYTES>>>(AOp, WoT, bo, out, 1.0f);
}

// round 9
// speedup vs baseline: 2.1216x; 1.8593x over previous
#include <cuda_runtime.h>
#include <cuda_fp16.h>
#include <math.h>
#include <stdint.h>

#define BATCH  4
#define SEQ    2048
#define DMODEL 1024
#define NHEAD  16
#define DHEAD  64
#define MROWS  (BATCH*SEQ)   // 8192

// fp16 scratch. g_V stored TRANSPOSED [b,h,dh,s]; g_Q pre-scaled by SSCALE.
__device__ __half g_Q [BATCH*NHEAD*SEQ*DHEAD];
__device__ __half g_K [BATCH*NHEAD*SEQ*DHEAD];
__device__ __half g_V [BATCH*NHEAD*SEQ*DHEAD];
__device__ __half g_AO[(size_t)MROWS*DMODEL];
__device__ __half g_X [(size_t)MROWS*DMODEL];
__device__ __half g_W4[4][(size_t)DMODEL*DMODEL];

#define SSCALE 0.18033688011112042f   // 0.125 * log2(e)

// ---------------------------------------------------------------------------
__device__ __forceinline__ float ex2f(float x) {
    float r;
    asm("ex2.approx.ftz.f32 %0, %1;" : "=f"(r) : "f"(x));
    return r;
}
__device__ __forceinline__ void mma_f16(float* d, const uint32_t* a,
                                        uint32_t b0, uint32_t b1) {
    asm volatile(
        "mma.sync.aligned.m16n8k16.row.col.f32.f16.f16.f32 "
        "{%0,%1,%2,%3}, {%4,%5,%6,%7}, {%8,%9}, {%0,%1,%2,%3};"
        : "+f"(d[0]), "+f"(d[1]), "+f"(d[2]), "+f"(d[3])
        : "r"(a[0]), "r"(a[1]), "r"(a[2]), "r"(a[3]),
          "r"(b0), "r"(b1));
}
__device__ __forceinline__ void ldsm_x4(uint32_t* r, uint32_t addr) {
    asm volatile("ldmatrix.sync.aligned.m8n8.x4.shared.b16 {%0,%1,%2,%3}, [%4];"
        : "=r"(r[0]), "=r"(r[1]), "=r"(r[2]), "=r"(r[3]) : "r"(addr));
}
__device__ __forceinline__ uint32_t smem_u32(const void* p) {
    uint32_t a;
    asm("{ .reg .u64 t; cvta.to.shared.u64 t, %1; cvt.u32.u64 %0, t; }" : "=r"(a) : "l"(p));
    return a;
}
__device__ __forceinline__ void cp_async16(uint32_t dst, const void* src) {
    asm volatile("cp.async.ca.shared.global [%0], [%1], 16;" :: "r"(dst), "l"(src));
}
__device__ __forceinline__ void cp_commit() {
    asm volatile("cp.async.commit_group;" ::: "memory");
}
template<int N>
__device__ __forceinline__ void cp_wait() {
    asm volatile("cp.async.wait_group %0;" :: "n"(N) : "memory");
}

// ---------------------------------------------------------------------------
// fp32 -> fp16 elementwise
__global__ void cvt_f16_pass(const float* __restrict__ in,
                             __half* __restrict__ outp, int n4) {
    const int i = blockIdx.x * blockDim.x + threadIdx.x;
    if (i < n4) {
        float4 v = *reinterpret_cast<const float4*>(in + (size_t)i * 4);
        __half2 h0 = __floats2half2_rn(v.x, v.y);
        __half2 h1 = __floats2half2_rn(v.z, v.w);
        *reinterpret_cast<uint2*>(outp + (size_t)i * 4) =
            make_uint2(*(uint32_t*)&h0, *(uint32_t*)&h1);
    }
}

// WT[n][k] = fp16(W[k][n]) for 4 weight matrices
__global__ void transpose_cvt4(const float* __restrict__ W0,
                               const float* __restrict__ W1,
                               const float* __restrict__ W2,
                               const float* __restrict__ W3,
                               __half* __restrict__ WT) {
    __shared__ float tbuf[32][33];
    const float* W = (blockIdx.z == 0) ? W0 : (blockIdx.z == 1) ? W1
                   : (blockIdx.z == 2) ? W2 : W3;
    __half* T = WT + (size_t)blockIdx.z * DMODEL * DMODEL;
    const int bx = blockIdx.x * 32, by = blockIdx.y * 32;
#pragma unroll
    for (int i = 0; i < 32; i += 8)
        tbuf[threadIdx.y + i][threadIdx.x] =
            W[(size_t)(by + threadIdx.y + i) * DMODEL + bx + threadIdx.x];
    __syncthreads();
#pragma unroll
    for (int i = 0; i < 32; i += 8)
        T[(size_t)(bx + threadIdx.y + i) * DMODEL + by + threadIdx.x] =
            __float2half_rn(tbuf[threadIdx.x][threadIdx.y + i]);
}

// ---------------------------------------------------------------------------
// fp16 GEMM: C = (A @ WT^T + bias) * oscale. BK=64 halves, 2-stage cp.async,
// all fragments via ldmatrix b16, m16n8k16.
// REMAP: 0 = plain fp32 [M][N], 1 = fp16 [b,h,s,dh], 2 = fp16 V-T [b,h,dh,s].
// ---------------------------------------------------------------------------
#define TPITCH 72                   // halves per row
#define T_ST   (128*TPITCH)         // 9216 halves per tile
#define GEMM_SMEM_BYTES (2*2*T_ST*2)   // 73728

template<int REMAP, int CVTOUT>
__global__ __launch_bounds__(256) void gemm_mma(
    const __half* __restrict__ A, const __half* __restrict__ WT,
    const float* __restrict__ bias, void* __restrict__ Cv, float oscale)
{
    extern __shared__ __half sh[];
    const uint32_t sbase = smem_u32(sh);

    const int tid  = threadIdx.x;
    const int wid  = tid >> 5, lane = tid & 31;
    const int g    = lane >> 2, t = lane & 3;
    const int m0   = blockIdx.y * 128, n0 = blockIdx.x * 128;
    const int wm0  = (wid >> 2) * 64, wn0 = (wid & 3) * 32;

    const int arow_l = (lane & 7) + ((lane >> 3) & 1) * 8;
    const int acol_l = (lane >> 4) * 8;                    // halves
    const int brow_l = (lane >> 4) * 8 + (lane & 7);
    const int bcol_l = ((lane >> 3) & 1) * 8;              // halves
    uint32_t aoff[4], boff[2];
#pragma unroll
    for (int mt = 0; mt < 4; mt++)
        aoff[mt] = (uint32_t)(((wm0 + mt * 16 + arow_l) * TPITCH + acol_l) * 2);
#pragma unroll
    for (int ntp = 0; ntp < 2; ntp++)
        boff[ntp] = (uint32_t)(((wn0 + ntp * 16 + brow_l) * TPITCH + bcol_l) * 2);

    // loaders: 1024 16B-chunks per tile (128 rows x 8), 4 per thread
    int lr[4], lc[4];
#pragma unroll
    for (int i = 0; i < 4; i++) {
        const int c = tid + i * 256;
        lr[i] = c >> 3;
        lc[i] = (c & 7) * 8;   // halves
    }

    auto issue = [&](int kt, int s) {
        const uint32_t abase = sbase + (uint32_t)(s * 2 * T_ST) * 2;
        const uint32_t bbase = abase + (uint32_t)T_ST * 2;
#pragma unroll
        for (int i = 0; i < 4; i++) {
            cp_async16(abase + (uint32_t)(lr[i] * TPITCH + lc[i]) * 2,
                       A + (size_t)(m0 + lr[i]) * DMODEL + kt * 64 + lc[i]);
            cp_async16(bbase + (uint32_t)(lr[i] * TPITCH + lc[i]) * 2,
                       WT + (size_t)(n0 + lr[i]) * DMODEL + kt * 64 + lc[i]);
        }
        cp_commit();
    };

    float acc[4][4][4];
#pragma unroll
    for (int mt = 0; mt < 4; mt++)
#pragma unroll
        for (int nt = 0; nt < 4; nt++)
#pragma unroll
            for (int r = 0; r < 4; r++) acc[mt][nt][r] = 0.f;

    issue(0, 0);

    const int NKT = DMODEL / 64;   // 16
    for (int kt = 0; kt < NKT; kt++) {
        const int s = kt & 1;
        cp_wait<0>();
        __syncthreads();
        if (kt + 1 < NKT) issue(kt + 1, s ^ 1);

        const uint32_t abase = sbase + (uint32_t)(s * 2 * T_ST) * 2;
        const uint32_t bbase = abase + (uint32_t)T_ST * 2;
#pragma unroll
        for (int kg = 0; kg < 4; kg++) {
            const uint32_t kb = (uint32_t)(kg * 32);   // 16 halves
            uint32_t af[4][4], bf[2][4];
#pragma unroll
            for (int mt = 0; mt < 4; mt++)
                ldsm_x4(af[mt], abase + aoff[mt] + kb);
#pragma unroll
            for (int ntp = 0; ntp < 2; ntp++)
                ldsm_x4(bf[ntp], bbase + boff[ntp] + kb);
#pragma unroll
            for (int mt = 0; mt < 4; mt++)
#pragma unroll
                for (int ntp = 0; ntp < 2; ntp++) {
                    mma_f16(acc[mt][2*ntp],   af[mt], bf[ntp][0], bf[ntp][1]);
                    mma_f16(acc[mt][2*ntp+1], af[mt], bf[ntp][2], bf[ntp][3]);
                }
        }
    }

#pragma unroll
    for (int mt = 0; mt < 4; mt++) {
#pragma unroll
        for (int nt = 0; nt < 4; nt++) {
            const int row = m0 + wm0 + mt * 16 + g;
            const int col = n0 + wn0 + nt * 8 + t * 2;
            const float b0 = bias[col], b1 = bias[col + 1];
#pragma unroll
            for (int half = 0; half < 2; half++) {
                const int m = row + half * 8;
                const float v0 = (acc[mt][nt][half*2]   + b0) * oscale;
                const float v1 = (acc[mt][nt][half*2+1] + b1) * oscale;
                if (REMAP == 2) {
                    __half* C = (__half*)Cv;
                    const int bb = m >> 11, ss = m & 2047;
                    const int hh = col >> 6, dd = col & 63;
                    __half* vt = C + (((size_t)(bb * NHEAD + hh) * DHEAD + dd) * SEQ + ss);
                    vt[0]   = __float2half_rn(v0);
                    vt[SEQ] = __float2half_rn(v1);
                } else if (REMAP == 1) {
                    __half* C = (__half*)Cv;
                    const int bb = m >> 11, ss = m & 2047;
                    const int hh = col >> 6, dd = col & 63;
                    __half2 h = __floats2half2_rn(v0, v1);
                    *reinterpret_cast<__half2*>(
                        C + (((size_t)(bb * NHEAD + hh) * SEQ + ss) * DHEAD + dd)) = h;
                } else {
                    float* C = (float*)Cv;
                    *reinterpret_cast<float2*>(C + (size_t)m * DMODEL + col) =
                        make_float2(v0, v1);
                }
            }
        }
    }
}

// ---------------------------------------------------------------------------
// Flash attention fp16 m16n8k16, single-buffered K/V with split overlap,
// log2-domain softmax. All tiles 64 x 72 halves (9216 B each).
// ---------------------------------------------------------------------------
#define FP 72
#define FQ_B 0
#define FK_B 9216
#define FV_B 18432
#define FP_B 27648
#define FA_SMEM_BYTES 36864

__global__ __launch_bounds__(128) void flash_attn_mma(
    const __half* __restrict__ Q, const __half* __restrict__ K,
    const __half* __restrict__ V, __half* __restrict__ AO,
    const int* __restrict__ maskp)
{
    extern __shared__ __half sh[];
    const uint32_t sbase = smem_u32(sh);
    __half* Ps = sh + FP_B / 2;

    const int tid = threadIdx.x;
    const int wid = tid >> 5, lane = tid & 31;
    const int g = lane >> 2, t = lane & 3;
    const int qt = blockIdx.x, hh = blockIdx.y, bb = blockIdx.z;
    const int q0 = qt * 64;
    const int wr0 = wid * 16;
    const size_t bh = ((size_t)bb*NHEAD + hh) * SEQ * DHEAD;
    const int causal = (maskp[0] != 0);
    const int ktmax = causal ? qt : (SEQ/64 - 1);

    const int arow_l = (lane & 7) + ((lane >> 3) & 1) * 8;
    const int acol_l = (lane >> 4) * 8;
    const int brow_l = (lane >> 4) * 8 + (lane & 7);
    const int bcol_l = ((lane >> 3) & 1) * 8;
    const uint32_t qoff = (uint32_t)(((wr0 + arow_l) * FP + acol_l) * 2);
    const uint32_t koff = (uint32_t)((brow_l * FP + bcol_l) * 2);

    const uint32_t qbase = sbase + FQ_B;
    const uint32_t kbase = sbase + FK_B;
    const uint32_t vbase = sbase + FV_B;
    const uint32_t pbase = sbase + FP_B;

    // 512 16B-chunks per tile (64 rows x 8), 4 per thread
    auto issue_k = [&](int kt) {
        const __half* Kg = K + bh + (size_t)kt*64*DHEAD;
#pragma unroll
        for (int i = 0; i < 4; i++) {
            const int c = tid + i * 128;
            const int r = c >> 3, col = (c & 7) * 8;
            cp_async16(kbase + (uint32_t)(r*FP + col) * 2, Kg + r*DHEAD + col);
        }
        cp_commit();
    };
    auto issue_v = [&](int kt) {
        const __half* Vg = V + bh;   // transposed [dh][s]
#pragma unroll
        for (int i = 0; i < 4; i++) {
            const int c = tid + i * 128;
            const int r = c >> 3, col = (c & 7) * 8;
            cp_async16(vbase + (uint32_t)(r*FP + col) * 2,
                       Vg + (size_t)r*SEQ + kt*64 + col);
        }
        cp_commit();
    };

    {   // prologue: group0 = Q + K0, group1 = V0
        const __half* Qg = Q + bh + (size_t)q0 * DHEAD;
#pragma unroll
        for (int i = 0; i < 4; i++) {
            const int c = tid + i * 128;
            const int r = c >> 3, col = (c & 7) * 8;
            cp_async16(qbase + (uint32_t)(r*FP + col) * 2, Qg + r*DHEAD + col);
        }
        issue_k(0);
        issue_v(0);
    }

    float m_i[2] = { -INFINITY, -INFINITY };
    float l_i[2] = { 0.f, 0.f };
    float accO[8][4];
#pragma unroll
    for (int nt = 0; nt < 8; nt++)
#pragma unroll
        for (int c = 0; c < 4; c++) accO[nt][c] = 0.f;

    for (int kt = 0; kt <= ktmax; kt++) {
        cp_wait<1>();      // Q + K_kt ready
        __syncthreads();

        // S = Q @ K^T (warp: 16x64)
        float accS[8][4];
#pragma unroll
        for (int nt = 0; nt < 8; nt++)
#pragma unroll
            for (int c = 0; c < 4; c++) accS[nt][c] = 0.f;
#pragma unroll
        for (int kg = 0; kg < 4; kg++) {
            const uint32_t kb = (uint32_t)(kg * 32);
            uint32_t af[4];
            ldsm_x4(af, qbase + qoff + kb);
#pragma unroll
            for (int ntp = 0; ntp < 4; ntp++) {
                uint32_t kr[4];
                ldsm_x4(kr, kbase + (uint32_t)(ntp * 16 * FP * 2) + koff + kb);
                mma_f16(accS[2*ntp],   af, kr[0], kr[1]);
                mma_f16(accS[2*ntp+1], af, kr[2], kr[3]);
            }
        }

        __syncthreads();                    // K buffer free
        if (kt + 1 <= ktmax) issue_k(kt + 1);

        const bool diag = causal && (kt == qt);
        if (diag) {
#pragma unroll
            for (int nt = 0; nt < 8; nt++)
#pragma unroll
                for (int c = 0; c < 4; c++) {
                    const int grow = q0 + wr0 + g + ((c & 2) ? 8 : 0);
                    const int gcol = kt*64 + nt*8 + 2*t + (c & 1);
                    if (gcol > grow) accS[nt][c] = -INFINITY;
                }
        }

#pragma unroll
        for (int r = 0; r < 2; r++) {
            float rmax = -INFINITY;
#pragma unroll
            for (int nt = 0; nt < 8; nt++)
                rmax = fmaxf(rmax, fmaxf(accS[nt][2*r], accS[nt][2*r+1]));
            rmax = fmaxf(rmax, __shfl_xor_sync(0xffffffffu, rmax, 1));
            rmax = fmaxf(rmax, __shfl_xor_sync(0xffffffffu, rmax, 2));
            const float mnew = fmaxf(m_i[r], rmax);
            const float corr = ex2f(m_i[r] - mnew);
            m_i[r] = mnew;
            float rsum = 0.f;
#pragma unroll
            for (int nt = 0; nt < 8; nt++) {
                const float p0 = ex2f(accS[nt][2*r]   - mnew);
                const float p1 = ex2f(accS[nt][2*r+1] - mnew);
                accS[nt][2*r] = p0; accS[nt][2*r+1] = p1;
                rsum += p0 + p1;
            }
            rsum += __shfl_xor_sync(0xffffffffu, rsum, 1);
            rsum += __shfl_xor_sync(0xffffffffu, rsum, 2);
            l_i[r] = l_i[r] * corr + rsum;
#pragma unroll
            for (int nt = 0; nt < 8; nt++) {
                accO[nt][2*r]   *= corr;
                accO[nt][2*r+1] *= corr;
            }
        }

        // stage P (fp16), warp-private rows
#pragma unroll
        for (int nt = 0; nt < 8; nt++) {
            *reinterpret_cast<__half2*>(Ps + (wr0 + g)*FP + nt*8 + 2*t) =
                __floats2half2_rn(accS[nt][0], accS[nt][1]);
            *reinterpret_cast<__half2*>(Ps + (wr0 + g + 8)*FP + nt*8 + 2*t) =
                __floats2half2_rn(accS[nt][2], accS[nt][3]);
        }
        __syncwarp();

        if (kt < ktmax) cp_wait<1>(); else cp_wait<0>();   // V_kt ready
        __syncthreads();

        // O += P @ V (V tile [dh][kv])
#pragma unroll
        for (int kg = 0; kg < 4; kg++) {
            const uint32_t kb = (uint32_t)(kg * 32);
            uint32_t af[4];
            ldsm_x4(af, pbase + qoff + kb);
#pragma unroll
            for (int ntp = 0; ntp < 4; ntp++) {
                uint32_t vr[4];
                ldsm_x4(vr, vbase + (uint32_t)(ntp * 16 * FP * 2) + koff + kb);
                mma_f16(accO[2*ntp],   af, vr[0], vr[1]);
                mma_f16(accO[2*ntp+1], af, vr[2], vr[3]);
            }
        }

        __syncthreads();                    // V buffer free
        if (kt + 1 <= ktmax) issue_v(kt + 1);
    }

    const float inv0 = 1.f / l_i[0];
    const float inv1 = 1.f / l_i[1];
    const int row0 = q0 + wr0 + g;
    __half* outb = AO + ((size_t)bb*SEQ + row0)*DMODEL + hh*DHEAD;
#pragma unroll
    for (int nt = 0; nt < 8; nt++) {
        const int col = nt*8 + 2*t;
        *reinterpret_cast<__half2*>(outb + col) =
            __floats2half2_rn(accO[nt][0]*inv0, accO[nt][1]*inv0);
        *reinterpret_cast<__half2*>(outb + 8*DMODEL + col) =
            __floats2half2_rn(accO[nt][2]*inv1, accO[nt][3]*inv1);
    }
}

// ---------------------------------------------------------------------------
extern "C" void kernel_launch(void* const* d_in, const int* in_sizes, int n_in,
                              void* d_out, int out_size)
{
    const float* x    = (const float*)d_in[0];
    const float* Wq   = (const float*)d_in[1];
    const float* bq   = (const float*)d_in[2];
    const float* Wk   = (const float*)d_in[3];
    const float* bk   = (const float*)d_in[4];
    const float* Wv   = (const float*)d_in[5];
    const float* bv   = (const float*)d_in[6];
    const float* Wo   = (const float*)d_in[7];
    const float* bo   = (const float*)d_in[8];
    const int*   mask = (const int*)  d_in[9];
    float* out = (float*)d_out;

    __half *Qp, *Kp, *Vp, *AOp, *Xp, *Wp;
    cudaGetSymbolAddress((void**)&Qp,  g_Q);
    cudaGetSymbolAddress((void**)&Kp,  g_K);
    cudaGetSymbolAddress((void**)&Vp,  g_V);
    cudaGetSymbolAddress((void**)&AOp, g_AO);
    cudaGetSymbolAddress((void**)&Xp,  g_X);
    cudaGetSymbolAddress((void**)&Wp,  g_W4);
    __half* WqT = Wp + 0 * (size_t)DMODEL*DMODEL;
    __half* WkT = Wp + 1 * (size_t)DMODEL*DMODEL;
    __half* WvT = Wp + 2 * (size_t)DMODEL*DMODEL;
    __half* WoT = Wp + 3 * (size_t)DMODEL*DMODEL;

    cudaFuncSetAttribute(gemm_mma<1,1>, cudaFuncAttributeMaxDynamicSharedMemorySize, GEMM_SMEM_BYTES);
    cudaFuncSetAttribute(gemm_mma<2,1>, cudaFuncAttributeMaxDynamicSharedMemorySize, GEMM_SMEM_BYTES);
    cudaFuncSetAttribute(gemm_mma<0,0>, cudaFuncAttributeMaxDynamicSharedMemorySize, GEMM_SMEM_BYTES);
    cudaFuncSetAttribute(flash_attn_mma, cudaFuncAttributeMaxDynamicSharedMemorySize, FA_SMEM_BYTES);

    const int nx4 = MROWS * DMODEL / 4;
    cvt_f16_pass<<<(nx4 + 255)/256, 256>>>(x, Xp, nx4);
    dim3 tb(32, 8), tg4(32, 32, 4);
    transpose_cvt4<<<tg4, tb>>>(Wq, Wk, Wv, Wo, Wp);

    dim3 gg(DMODEL/128, MROWS/128);   // (8, 64)
    gemm_mma<1,1><<<gg, 256, GEMM_SMEM_BYTES>>>(Xp, WqT, bq, Qp, SSCALE);
    gemm_mma<1,1><<<gg, 256, GEMM_SMEM_BYTES>>>(Xp, WkT, bk, Kp, 1.0f);
    gemm_mma<2,1><<<gg, 256, GEMM_SMEM_BYTES>>>(Xp, WvT, bv, Vp, 1.0f);

    dim3 gattn(SEQ/64, NHEAD, BATCH);  // (32, 16, 4)
    flash_attn_mma<<<gattn, 128, FA_SMEM_BYTES>>>(Qp, Kp, Vp, AOp, mask);

    gemm_mma<0,0><<<gg, 256, GEMM_SMEM_BYTES>>>(AOp, WoT, bo, out, 1.0f);
}

// round 10
// speedup vs baseline: 2.3577x; 1.1112x over previous
#include <cuda_runtime.h>
#include <cuda_fp16.h>
#include <math.h>
#include <stdint.h>

#define BATCH  4
#define SEQ    2048
#define DMODEL 1024
#define NHEAD  16
#define DHEAD  64
#define MROWS  (BATCH*SEQ)   // 8192

// fp16 scratch. g_V stored TRANSPOSED [b,h,dh,s]; g_Q pre-scaled by SSCALE.
__device__ __half g_Q [BATCH*NHEAD*SEQ*DHEAD];
__device__ __half g_K [BATCH*NHEAD*SEQ*DHEAD];
__device__ __half g_V [BATCH*NHEAD*SEQ*DHEAD];
__device__ __half g_AO[(size_t)MROWS*DMODEL];
__device__ __half g_X [(size_t)MROWS*DMODEL];
__device__ __half g_W4[4][(size_t)DMODEL*DMODEL];   // WqT|WkT|WvT|WoT

#define SSCALE 0.18033688011112042f   // 0.125 * log2(e)

// ---------------------------------------------------------------------------
__device__ __forceinline__ float ex2f(float x) {
    float r;
    asm("ex2.approx.ftz.f32 %0, %1;" : "=f"(r) : "f"(x));
    return r;
}
__device__ __forceinline__ void mma_f16(float* d, const uint32_t* a,
                                        uint32_t b0, uint32_t b1) {
    asm volatile(
        "mma.sync.aligned.m16n8k16.row.col.f32.f16.f16.f32 "
        "{%0,%1,%2,%3}, {%4,%5,%6,%7}, {%8,%9}, {%0,%1,%2,%3};"
        : "+f"(d[0]), "+f"(d[1]), "+f"(d[2]), "+f"(d[3])
        : "r"(a[0]), "r"(a[1]), "r"(a[2]), "r"(a[3]),
          "r"(b0), "r"(b1));
}
__device__ __forceinline__ void ldsm_x4(uint32_t* r, uint32_t addr) {
    asm volatile("ldmatrix.sync.aligned.m8n8.x4.shared.b16 {%0,%1,%2,%3}, [%4];"
        : "=r"(r[0]), "=r"(r[1]), "=r"(r[2]), "=r"(r[3]) : "r"(addr));
}
__device__ __forceinline__ uint32_t smem_u32(const void* p) {
    uint32_t a;
    asm("{ .reg .u64 t; cvta.to.shared.u64 t, %1; cvt.u32.u64 %0, t; }" : "=r"(a) : "l"(p));
    return a;
}
__device__ __forceinline__ void cp_async16(uint32_t dst, const void* src) {
    asm volatile("cp.async.ca.shared.global [%0], [%1], 16;" :: "r"(dst), "l"(src));
}
__device__ __forceinline__ void cp_commit() {
    asm volatile("cp.async.commit_group;" ::: "memory");
}
template<int N>
__device__ __forceinline__ void cp_wait() {
    asm volatile("cp.async.wait_group %0;" :: "n"(N) : "memory");
}
__device__ __forceinline__ uint32_t packh2(float a, float b) {
    __half2 h = __floats2half2_rn(a, b);
    return *reinterpret_cast<uint32_t*>(&h);
}

// ---------------------------------------------------------------------------
__global__ void cvt_f16_pass(const float* __restrict__ in,
                             __half* __restrict__ outp, int n4) {
    const int i = blockIdx.x * blockDim.x + threadIdx.x;
    if (i < n4) {
        float4 v = *reinterpret_cast<const float4*>(in + (size_t)i * 4);
        __half2 h0 = __floats2half2_rn(v.x, v.y);
        __half2 h1 = __floats2half2_rn(v.z, v.w);
        *reinterpret_cast<uint2*>(outp + (size_t)i * 4) =
            make_uint2(*(uint32_t*)&h0, *(uint32_t*)&h1);
    }
}

__global__ void transpose_cvt4(const float* __restrict__ W0,
                               const float* __restrict__ W1,
                               const float* __restrict__ W2,
                               const float* __restrict__ W3,
                               __half* __restrict__ WT) {
    __shared__ float tbuf[32][33];
    const float* W = (blockIdx.z == 0) ? W0 : (blockIdx.z == 1) ? W1
                   : (blockIdx.z == 2) ? W2 : W3;
    __half* T = WT + (size_t)blockIdx.z * DMODEL * DMODEL;
    const int bx = blockIdx.x * 32, by = blockIdx.y * 32;
#pragma unroll
    for (int i = 0; i < 32; i += 8)
        tbuf[threadIdx.y + i][threadIdx.x] =
            W[(size_t)(by + threadIdx.y + i) * DMODEL + bx + threadIdx.x];
    __syncthreads();
#pragma unroll
    for (int i = 0; i < 32; i += 8)
        T[(size_t)(bx + threadIdx.y + i) * DMODEL + by + threadIdx.x] =
            __float2half_rn(tbuf[threadIdx.x][threadIdx.y + i]);
}

// ---------------------------------------------------------------------------
// fp16 GEMM, BK=64, 2-stage cp.async, m16n8k16, ldmatrix everywhere.
// FUSED=1: N spans 3 concatenated weights (Q|K|V); sel = n0>>10 picks
//          bias/scale/output. FUSED=0: O-projection, fp32 out.
// ---------------------------------------------------------------------------
#define TPITCH 72
#define T_ST   (128*TPITCH)
#define GEMM_SMEM_BYTES (2*2*T_ST*2)   // 73728

template<int FUSED>
__global__ __launch_bounds__(256) void gemm_mma(
    const __half* __restrict__ A, const __half* __restrict__ WT,
    const float* __restrict__ bq, const float* __restrict__ bk,
    const float* __restrict__ bv,
    void* __restrict__ Cq, void* __restrict__ Ck, void* __restrict__ Cv)
{
    extern __shared__ __half sh[];
    const uint32_t sbase = smem_u32(sh);

    const int tid  = threadIdx.x;
    const int wid  = tid >> 5, lane = tid & 31;
    const int g    = lane >> 2, t = lane & 3;
    const int m0   = blockIdx.y * 128, n0 = blockIdx.x * 128;
    const int wm0  = (wid >> 2) * 64, wn0 = (wid & 3) * 32;

    const int sel = FUSED ? (n0 >> 10) : 0;
    const float* bias = FUSED ? (sel == 0 ? bq : sel == 1 ? bk : bv) : bq;
    const float oscale = (FUSED && sel == 0) ? SSCALE : 1.0f;
    void* Cout = FUSED ? (sel == 0 ? Cq : sel == 1 ? Ck : Cv) : Cq;
    const int ncol0 = FUSED ? (n0 & 1023) : n0;

    const int arow_l = (lane & 7) + ((lane >> 3) & 1) * 8;
    const int acol_l = (lane >> 4) * 8;
    const int brow_l = (lane >> 4) * 8 + (lane & 7);
    const int bcol_l = ((lane >> 3) & 1) * 8;
    uint32_t aoff[4], boff[2];
#pragma unroll
    for (int mt = 0; mt < 4; mt++)
        aoff[mt] = (uint32_t)(((wm0 + mt * 16 + arow_l) * TPITCH + acol_l) * 2);
#pragma unroll
    for (int ntp = 0; ntp < 2; ntp++)
        boff[ntp] = (uint32_t)(((wn0 + ntp * 16 + brow_l) * TPITCH + bcol_l) * 2);

    int lr[4], lc[4];
#pragma unroll
    for (int i = 0; i < 4; i++) {
        const int c = tid + i * 256;
        lr[i] = c >> 3;
        lc[i] = (c & 7) * 8;
    }

    auto issue = [&](int kt, int s) {
        const uint32_t abase = sbase + (uint32_t)(s * 2 * T_ST) * 2;
        const uint32_t bbase = abase + (uint32_t)T_ST * 2;
#pragma unroll
        for (int i = 0; i < 4; i++) {
            cp_async16(abase + (uint32_t)(lr[i] * TPITCH + lc[i]) * 2,
                       A + (size_t)(m0 + lr[i]) * DMODEL + kt * 64 + lc[i]);
            cp_async16(bbase + (uint32_t)(lr[i] * TPITCH + lc[i]) * 2,
                       WT + (size_t)(n0 + lr[i]) * DMODEL + kt * 64 + lc[i]);
        }
        cp_commit();
    };

    float acc[4][4][4];
#pragma unroll
    for (int mt = 0; mt < 4; mt++)
#pragma unroll
        for (int nt = 0; nt < 4; nt++)
#pragma unroll
            for (int r = 0; r < 4; r++) acc[mt][nt][r] = 0.f;

    issue(0, 0);

    const int NKT = DMODEL / 64;   // 16
    for (int kt = 0; kt < NKT; kt++) {
        const int s = kt & 1;
        cp_wait<0>();
        __syncthreads();
        if (kt + 1 < NKT) issue(kt + 1, s ^ 1);

        const uint32_t abase = sbase + (uint32_t)(s * 2 * T_ST) * 2;
        const uint32_t bbase = abase + (uint32_t)T_ST * 2;
#pragma unroll
        for (int kg = 0; kg < 4; kg++) {
            const uint32_t kb = (uint32_t)(kg * 32);
            uint32_t af[4][4], bf[2][4];
#pragma unroll
            for (int mt = 0; mt < 4; mt++)
                ldsm_x4(af[mt], abase + aoff[mt] + kb);
#pragma unroll
            for (int ntp = 0; ntp < 2; ntp++)
                ldsm_x4(bf[ntp], bbase + boff[ntp] + kb);
#pragma unroll
            for (int mt = 0; mt < 4; mt++)
#pragma unroll
                for (int ntp = 0; ntp < 2; ntp++) {
                    mma_f16(acc[mt][2*ntp],   af[mt], bf[ntp][0], bf[ntp][1]);
                    mma_f16(acc[mt][2*ntp+1], af[mt], bf[ntp][2], bf[ntp][3]);
                }
        }
    }

#pragma unroll
    for (int mt = 0; mt < 4; mt++) {
#pragma unroll
        for (int nt = 0; nt < 4; nt++) {
            const int row = m0 + wm0 + mt * 16 + g;
            const int col = ncol0 + wn0 + nt * 8 + t * 2;
            const float b0 = bias[col], b1 = bias[col + 1];
#pragma unroll
            for (int half = 0; half < 2; half++) {
                const int m = row + half * 8;
                const float v0 = (acc[mt][nt][half*2]   + b0) * oscale;
                const float v1 = (acc[mt][nt][half*2+1] + b1) * oscale;
                if (FUSED) {
                    __half* C = (__half*)Cout;
                    const int bb = m >> 11, ss = m & 2047;
                    const int hh = col >> 6, dd = col & 63;
                    if (sel == 2) {   // V transposed [b,h,dh,s]
                        __half* vt = C + (((size_t)(bb * NHEAD + hh) * DHEAD + dd) * SEQ + ss);
                        vt[0]   = __float2half_rn(v0);
                        vt[SEQ] = __float2half_rn(v1);
                    } else {          // Q/K: [b,h,s,dh]
                        *reinterpret_cast<__half2*>(
                            C + (((size_t)(bb * NHEAD + hh) * SEQ + ss) * DHEAD + dd)) =
                            __floats2half2_rn(v0, v1);
                    }
                } else {
                    float* C = (float*)Cout;
                    *reinterpret_cast<float2*>(C + (size_t)m * DMODEL + col) =
                        make_float2(v0, v1);
                }
            }
        }
    }
}

// ---------------------------------------------------------------------------
// Flash attention fp16: register-resident P (no SMEM staging), single-buffered
// K/V with split overlap, log2-domain softmax. smem = 27648 B.
// ---------------------------------------------------------------------------
#define FP 72
#define FQ_B 0
#define FK_B 9216
#define FV_B 18432
#define FA_SMEM_BYTES 27648

__global__ __launch_bounds__(128) void flash_attn_mma(
    const __half* __restrict__ Q, const __half* __restrict__ K,
    const __half* __restrict__ V, __half* __restrict__ AO,
    const int* __restrict__ maskp)
{
    extern __shared__ __half sh[];
    const uint32_t sbase = smem_u32(sh);

    const int tid = threadIdx.x;
    const int wid = tid >> 5, lane = tid & 31;
    const int g = lane >> 2, t = lane & 3;
    const int qt = blockIdx.x, hh = blockIdx.y, bb = blockIdx.z;
    const int q0 = qt * 64;
    const int wr0 = wid * 16;
    const size_t bh = ((size_t)bb*NHEAD + hh) * SEQ * DHEAD;
    const int causal = (maskp[0] != 0);
    const int ktmax = causal ? qt : (SEQ/64 - 1);

    const int arow_l = (lane & 7) + ((lane >> 3) & 1) * 8;
    const int acol_l = (lane >> 4) * 8;
    const int brow_l = (lane >> 4) * 8 + (lane & 7);
    const int bcol_l = ((lane >> 3) & 1) * 8;
    const uint32_t qoff = (uint32_t)(((wr0 + arow_l) * FP + acol_l) * 2);
    const uint32_t koff = (uint32_t)((brow_l * FP + bcol_l) * 2);

    const uint32_t qbase = sbase + FQ_B;
    const uint32_t kbase = sbase + FK_B;
    const uint32_t vbase = sbase + FV_B;

    auto issue_k = [&](int kt) {
        const __half* Kg = K + bh + (size_t)kt*64*DHEAD;
#pragma unroll
        for (int i = 0; i < 4; i++) {
            const int c = tid + i * 128;
            const int r = c >> 3, col = (c & 7) * 8;
            cp_async16(kbase + (uint32_t)(r*FP + col) * 2, Kg + r*DHEAD + col);
        }
        cp_commit();
    };
    auto issue_v = [&](int kt) {
        const __half* Vg = V + bh;
#pragma unroll
        for (int i = 0; i < 4; i++) {
            const int c = tid + i * 128;
            const int r = c >> 3, col = (c & 7) * 8;
            cp_async16(vbase + (uint32_t)(r*FP + col) * 2,
                       Vg + (size_t)r*SEQ + kt*64 + col);
        }
        cp_commit();
    };

    {   // prologue: group0 = Q + K0, group1 = V0
        const __half* Qg = Q + bh + (size_t)q0 * DHEAD;
#pragma unroll
        for (int i = 0; i < 4; i++) {
            const int c = tid + i * 128;
            const int r = c >> 3, col = (c & 7) * 8;
            cp_async16(qbase + (uint32_t)(r*FP + col) * 2, Qg + r*DHEAD + col);
        }
        issue_k(0);
        issue_v(0);
    }

    float m_i[2] = { -INFINITY, -INFINITY };
    float l_i[2] = { 0.f, 0.f };
    float accO[8][4];
#pragma unroll
    for (int nt = 0; nt < 8; nt++)
#pragma unroll
        for (int c = 0; c < 4; c++) accO[nt][c] = 0.f;

    for (int kt = 0; kt <= ktmax; kt++) {
        cp_wait<1>();      // Q + K_kt ready
        __syncthreads();

        // S = Q @ K^T (warp: 16x64)
        float accS[8][4];
#pragma unroll
        for (int nt = 0; nt < 8; nt++)
#pragma unroll
            for (int c = 0; c < 4; c++) accS[nt][c] = 0.f;
#pragma unroll
        for (int kg = 0; kg < 4; kg++) {
            const uint32_t kb = (uint32_t)(kg * 32);
            uint32_t af[4];
            ldsm_x4(af, qbase + qoff + kb);
#pragma unroll
            for (int ntp = 0; ntp < 4; ntp++) {
                uint32_t kr[4];
                ldsm_x4(kr, kbase + (uint32_t)(ntp * 16 * FP * 2) + koff + kb);
                mma_f16(accS[2*ntp],   af, kr[0], kr[1]);
                mma_f16(accS[2*ntp+1], af, kr[2], kr[3]);
            }
        }

        __syncthreads();                    // K buffer free
        if (kt + 1 <= ktmax) issue_k(kt + 1);

        const bool diag = causal && (kt == qt);
        if (diag) {
#pragma unroll
            for (int nt = 0; nt < 8; nt++)
#pragma unroll
                for (int c = 0; c < 4; c++) {
                    const int grow = q0 + wr0 + g + ((c & 2) ? 8 : 0);
                    const int gcol = kt*64 + nt*8 + 2*t + (c & 1);
                    if (gcol > grow) accS[nt][c] = -INFINITY;
                }
        }

#pragma unroll
        for (int r = 0; r < 2; r++) {
            float rmax = -INFINITY;
#pragma unroll
            for (int nt = 0; nt < 8; nt++)
                rmax = fmaxf(rmax, fmaxf(accS[nt][2*r], accS[nt][2*r+1]));
            rmax = fmaxf(rmax, __shfl_xor_sync(0xffffffffu, rmax, 1));
            rmax = fmaxf(rmax, __shfl_xor_sync(0xffffffffu, rmax, 2));
            const float mnew = fmaxf(m_i[r], rmax);
            const float corr = ex2f(m_i[r] - mnew);
            m_i[r] = mnew;
            float rsum = 0.f;
#pragma unroll
            for (int nt = 0; nt < 8; nt++) {
                const float p0 = ex2f(accS[nt][2*r]   - mnew);
                const float p1 = ex2f(accS[nt][2*r+1] - mnew);
                accS[nt][2*r] = p0; accS[nt][2*r+1] = p1;
                rsum += p0 + p1;
            }
            rsum += __shfl_xor_sync(0xffffffffu, rsum, 1);
            rsum += __shfl_xor_sync(0xffffffffu, rsum, 2);
            l_i[r] = l_i[r] * corr + rsum;
#pragma unroll
            for (int nt = 0; nt < 8; nt++) {
                accO[nt][2*r]   *= corr;
                accO[nt][2*r+1] *= corr;
            }
        }

        if (kt < ktmax) cp_wait<1>(); else cp_wait<0>();   // V_kt ready
        __syncthreads();

        // O += P @ V — P taken directly from accS registers (C-frag == A-frag)
#pragma unroll
        for (int kg = 0; kg < 4; kg++) {
            uint32_t af[4];
            af[0] = packh2(accS[2*kg][0],   accS[2*kg][1]);
            af[1] = packh2(accS[2*kg][2],   accS[2*kg][3]);
            af[2] = packh2(accS[2*kg+1][0], accS[2*kg+1][1]);
            af[3] = packh2(accS[2*kg+1][2], accS[2*kg+1][3]);
            const uint32_t kb = (uint32_t)(kg * 32);
#pragma unroll
            for (int ntp = 0; ntp < 4; ntp++) {
                uint32_t vr[4];
                ldsm_x4(vr, vbase + (uint32_t)(ntp * 16 * FP * 2) + koff + kb);
                mma_f16(accO[2*ntp],   af, vr[0], vr[1]);
                mma_f16(accO[2*ntp+1], af, vr[2], vr[3]);
            }
        }

        __syncthreads();                    // V buffer free
        if (kt + 1 <= ktmax) issue_v(kt + 1);
    }

    const float inv0 = 1.f / l_i[0];
    const float inv1 = 1.f / l_i[1];
    const int row0 = q0 + wr0 + g;
    __half* outb = AO + ((size_t)bb*SEQ + row0)*DMODEL + hh*DHEAD;
#pragma unroll
    for (int nt = 0; nt < 8; nt++) {
        const int col = nt*8 + 2*t;
        *reinterpret_cast<__half2*>(outb + col) =
            __floats2half2_rn(accO[nt][0]*inv0, accO[nt][1]*inv0);
        *reinterpret_cast<__half2*>(outb + 8*DMODEL + col) =
            __floats2half2_rn(accO[nt][2]*inv1, accO[nt][3]*inv1);
    }
}

// ---------------------------------------------------------------------------
extern "C" void kernel_launch(void* const* d_in, const int* in_sizes, int n_in,
                              void* d_out, int out_size)
{
    const float* x    = (const float*)d_in[0];
    const float* Wq   = (const float*)d_in[1];
    const float* bq   = (const float*)d_in[2];
    const float* Wk   = (const float*)d_in[3];
    const float* bk   = (const float*)d_in[4];
    const float* Wv   = (const float*)d_in[5];
    const float* bv   = (const float*)d_in[6];
    const float* Wo   = (const float*)d_in[7];
    const float* bo   = (const float*)d_in[8];
    const int*   mask = (const int*)  d_in[9];
    float* out = (float*)d_out;

    __half *Qp, *Kp, *Vp, *AOp, *Xp, *Wp;
    cudaGetSymbolAddress((void**)&Qp,  g_Q);
    cudaGetSymbolAddress((void**)&Kp,  g_K);
    cudaGetSymbolAddress((void**)&Vp,  g_V);
    cudaGetSymbolAddress((void**)&AOp, g_AO);
    cudaGetSymbolAddress((void**)&Xp,  g_X);
    cudaGetSymbolAddress((void**)&Wp,  g_W4);
    __half* WoT = Wp + 3 * (size_t)DMODEL*DMODEL;

    cudaFuncSetAttribute(gemm_mma<1>, cudaFuncAttributeMaxDynamicSharedMemorySize, GEMM_SMEM_BYTES);
    cudaFuncSetAttribute(gemm_mma<0>, cudaFuncAttributeMaxDynamicSharedMemorySize, GEMM_SMEM_BYTES);
    cudaFuncSetAttribute(flash_attn_mma, cudaFuncAttributeMaxDynamicSharedMemorySize, FA_SMEM_BYTES);

    const int nx4 = MROWS * DMODEL / 4;
    cvt_f16_pass<<<(nx4 + 255)/256, 256>>>(x, Xp, nx4);
    dim3 tb(32, 8), tg4(32, 32, 4);
    transpose_cvt4<<<tg4, tb>>>(Wq, Wk, Wv, Wo, Wp);

    // fused QKV projection: N = 3072 over WqT|WkT|WvT
    dim3 gq(3*DMODEL/128, MROWS/128);   // (24, 64)
    gemm_mma<1><<<gq, 256, GEMM_SMEM_BYTES>>>(Xp, Wp, bq, bk, bv,
                                              Qp, Kp, Vp);

    dim3 gattn(SEQ/64, NHEAD, BATCH);   // (32, 16, 4)
    flash_attn_mma<<<gattn, 128, FA_SMEM_BYTES>>>(Qp, Kp, Vp, AOp, mask);

    // output projection (fp32 out)
    dim3 go(DMODEL/128, MROWS/128);     // (8, 64)
    gemm_mma<0><<<go, 256, GEMM_SMEM_BYTES>>>(AOp, WoT, bo, bo, bo,
                                              out, out, out);
}